// round 12
// baseline (speedup 1.0000x reference)
#include <cuda_runtime.h>
#include <cstdint>

// ---------------- device scratch ----------------
__device__ __align__(16) float g_act0[32 * 21504];
__device__ __align__(16) float g_act3[32 * 4096];
__device__ __align__(16) float g_act4[32 * 64];
__device__ __align__(16) float g_part[1048576];        // max(2*32*16384, 8*32*4096)
__device__ __align__(16) uint4 g_xpk0[172032];         // 21504/16 * 128
__device__ __align__(16) uint4 g_xpk1[131072];         // 16384/16 * 128
__device__ __align__(16) uint4 g_xpk2[32768];          // 4096/16 * 128

// ---------------- PTX helpers ----------------
__device__ __forceinline__ void mma16816(float* d, unsigned a0, unsigned a1, unsigned a2, unsigned a3,
                                         unsigned b0, unsigned b1) {
    asm volatile("mma.sync.aligned.m16n8k16.row.col.f32.bf16.bf16.f32 "
                 "{%0,%1,%2,%3}, {%4,%5,%6,%7}, {%8,%9}, {%0,%1,%2,%3};"
                 : "+f"(d[0]), "+f"(d[1]), "+f"(d[2]), "+f"(d[3])
                 : "r"(a0), "r"(a1), "r"(a2), "r"(a3), "r"(b0), "r"(b1));
}
// float4 -> {hi01, hi23, lo01, lo23} packed bf16x2
__device__ __forceinline__ void cvt_hilo(float4 v, unsigned &h01, unsigned &h23,
                                         unsigned &l01, unsigned &l23) {
    asm("cvt.rn.bf16x2.f32 %0, %1, %2;" : "=r"(h01) : "f"(v.y), "f"(v.x));
    asm("cvt.rn.bf16x2.f32 %0, %1, %2;" : "=r"(h23) : "f"(v.w), "f"(v.z));
    float r0 = v.x - __uint_as_float(h01 << 16);
    float r1 = v.y - __uint_as_float(h01 & 0xffff0000u);
    float r2 = v.z - __uint_as_float(h23 << 16);
    float r3 = v.w - __uint_as_float(h23 & 0xffff0000u);
    asm("cvt.rn.bf16x2.f32 %0, %1, %2;" : "=r"(l01) : "f"(r1), "f"(r0));
    asm("cvt.rn.bf16x2.f32 %0, %1, %2;" : "=r"(l23) : "f"(r3), "f"(r2));
}

// ---------------- conv + permuted scatter ----------------
__global__ void conv_kernel(const float* __restrict__ in,
                            const float* __restrict__ cw,
                            const float* __restrict__ cb) {
    int b = blockIdx.x >> 2, f = blockIdx.x & 3, tid = threadIdx.x;
    __shared__ float xin[343], wsh[128], bsh[16];
    for (int i = tid; i < 343; i += 128) xin[i] = in[(b * 343 + i) * 5 + f];
    if (tid < 128) wsh[tid] = cw[tid];
    if (tid < 16)  bsh[tid] = cb[tid];
    __syncthreads();
    int h = b >> 4, base = (b & 15) * 1344 + f * 336;
    for (int l = tid; l < 336; l += 128) {
        #pragma unroll
        for (int c = 0; c < 16; ++c) {
            float s = bsh[c];
            #pragma unroll
            for (int k = 0; k < 8; ++k) s += xin[l + k] * wsh[c * 8 + k];
            g_act0[(2 * c + h) * 21504 + base + l] = fmaxf(s, 0.f);
        }
    }
}

// ---------------- pack fp32 X[32][K] -> fragment-ordered bf16 hi/lo uint4 ----------------
__global__ void pack_kernel(const float* __restrict__ src, int K, uint4* __restrict__ dst) {
    int i = blockIdx.x * 256 + threadIdx.x;
    if (i >= (K >> 4) * 128) return;
    int kb = i >> 7, ng = (i >> 5) & 3, lane = i & 31;
    int b = ng * 8 + (lane >> 2), c = kb * 16 + (lane & 3) * 4;
    float4 v = *(const float4*)(src + (long)b * K + c);
    uint4 o;
    cvt_hilo(v, o.x, o.y, o.z, o.w);
    dst[i] = o;
}

// ---------------- split-K reduce + bias + relu -> packed X ----------------
__global__ void reduce_pack(const float* __restrict__ bias, int N, int ks, uint4* __restrict__ dst) {
    int i = blockIdx.x * 256 + threadIdx.x;
    if (i >= (N >> 4) * 128) return;
    int kb = i >> 7, ng = (i >> 5) & 3, lane = i & 31;
    int b = ng * 8 + (lane >> 2), c = kb * 16 + (lane & 3) * 4;
    float4 s = *(const float4*)(bias + c);
    for (int si = 0; si < ks; ++si) {
        float4 p = *(const float4*)(g_part + ((long)(si * 32 + b)) * N + c);
        s.x += p.x; s.y += p.y; s.z += p.z; s.w += p.w;
    }
    s.x = fmaxf(s.x, 0.f); s.y = fmaxf(s.y, 0.f);
    s.z = fmaxf(s.z, 0.f); s.w = fmaxf(s.w, 0.f);
    uint4 o;
    cvt_hilo(s, o.x, o.y, o.z, o.w);
    dst[i] = o;
}

// ---------------- split-K reduce + bias + relu -> fp32 (dense4 input) ----------------
__global__ void reduce_kernel(const float* __restrict__ bias, int N, int ks) {
    int idx = blockIdx.x * 256 + threadIdx.x;
    if (idx >= 32 * N) return;
    float s = bias[idx % N];
    for (int si = 0; si < ks; ++si) s += g_part[(long)si * 32 * N + idx];
    g_act3[idx] = fmaxf(s, 0.f);
}

// ---------------- bf16x3 mma.sync GEMM: warps split M(4) x N(2) ----------------
// D[n,b] = sum_k W[n,k]*X[b,k]; tile M=128 x N=32, slab k=64, split-K raw partials.
__global__ __launch_bounds__(256, 2)
void gemm_mma(const float* __restrict__ W, const uint4* __restrict__ xpk,
              int N, int K, int nslabs) {
    int tid = threadIdx.x, wid = tid >> 5, lane = tid & 31;
    int mg = wid & 3, nh = wid >> 2;          // m-group 0..3 (32 rows), n-half 0..1
    int tile = blockIdx.x, ky = blockIdx.y;
    int r = lane >> 2, t = lane & 3;
    long k0 = (long)ky * nslabs * 64;

    const float* wp = W + (long)(tile * 128 + mg * 32 + r) * K + k0 + t * 4;
    long K8 = 8L * K, K16 = 16L * K;
    const uint4* xbase = xpk + (long)(ky * nslabs * 4) * 128 + (nh * 2) * 32 + lane;

    float acc[2][2][4];   // [m-frag][n-frag][4]
    #pragma unroll
    for (int i = 0; i < 2; ++i)
        #pragma unroll
        for (int j = 0; j < 2; ++j)
            #pragma unroll
            for (int q = 0; q < 4; ++q) acc[i][j][q] = 0.f;

    for (int s = 0; s < nslabs; ++s) {
        long sk = (long)s * 64;
        #pragma unroll
        for (int ks = 0; ks < 4; ++ks) {
            long ko = sk + ks * 16;
            unsigned ah[2][4], al[2][4];
            #pragma unroll
            for (int mi = 0; mi < 2; ++mi) {
                float4 w0 = __ldg((const float4*)(wp + mi * K16 + ko));
                float4 w1 = __ldg((const float4*)(wp + mi * K16 + K8 + ko));
                cvt_hilo(w0, ah[mi][0], ah[mi][2], al[mi][0], al[mi][2]);  // row r
                cvt_hilo(w1, ah[mi][1], ah[mi][3], al[mi][1], al[mi][3]);  // row r+8
            }
            const uint4* xq = xbase + (long)(s * 4 + ks) * 128;
            #pragma unroll
            for (int j = 0; j < 2; ++j) {
                uint4 u = __ldg(xq + j * 32);    // {bh0, bh1, bl0, bl1}
                #pragma unroll
                for (int mi = 0; mi < 2; ++mi) {
                    mma16816(acc[mi][j], ah[mi][0], ah[mi][1], ah[mi][2], ah[mi][3], u.x, u.y);
                    mma16816(acc[mi][j], ah[mi][0], ah[mi][1], ah[mi][2], ah[mi][3], u.z, u.w);
                    mma16816(acc[mi][j], al[mi][0], al[mi][1], al[mi][2], al[mi][3], u.x, u.y);
                }
            }
        }
    }

    // epilogue: raw split-K partials
    #pragma unroll
    for (int mi = 0; mi < 2; ++mi) {
        int n0 = tile * 128 + mg * 32 + mi * 16 + r;
        #pragma unroll
        for (int j = 0; j < 2; ++j) {
            int b0 = (nh * 2 + j) * 8 + 2 * t;
            g_part[(long)(ky * 32 + b0)     * N + n0]     = acc[mi][j][0];
            g_part[(long)(ky * 32 + b0 + 1) * N + n0]     = acc[mi][j][1];
            g_part[(long)(ky * 32 + b0)     * N + n0 + 8] = acc[mi][j][2];
            g_part[(long)(ky * 32 + b0 + 1) * N + n0 + 8] = acc[mi][j][3];
        }
    }
}

// ---------------- dense4 (4096 -> 64) ----------------
__global__ void dense4_kernel(const float* __restrict__ w4, const float* __restrict__ b4) {
    int n = blockIdx.x, tid = threadIdx.x;
    float acc[32];
    #pragma unroll
    for (int b = 0; b < 32; ++b) acc[b] = 0.f;
    const float* wr = w4 + n * 4096;
    for (int k = tid; k < 4096; k += 128) {
        float w = wr[k];
        #pragma unroll
        for (int b = 0; b < 32; ++b) acc[b] += g_act3[b * 4096 + k] * w;
    }
    __shared__ float red[4][32];
    int lane = tid & 31, wrp = tid >> 5;
    #pragma unroll
    for (int b = 0; b < 32; ++b) {
        float v = acc[b];
        v += __shfl_down_sync(0xffffffffu, v, 16);
        v += __shfl_down_sync(0xffffffffu, v, 8);
        v += __shfl_down_sync(0xffffffffu, v, 4);
        v += __shfl_down_sync(0xffffffffu, v, 2);
        v += __shfl_down_sync(0xffffffffu, v, 1);
        if (lane == 0) red[wrp][b] = v;
    }
    __syncthreads();
    if (tid < 32) {
        float s = red[0][tid] + red[1][tid] + red[2][tid] + red[3][tid] + b4[n];
        g_act4[tid * 64 + n] = fmaxf(s, 0.f);
    }
}

// ---------------- fused output (64 -> 16 -> 1) ----------------
__global__ void final_kernel(const float* __restrict__ wo, const float* __restrict__ bo,
                             const float* __restrict__ wf, const float* __restrict__ bf,
                             float* __restrict__ out) {
    int b = threadIdx.x;
    float res = bf[0];
    for (int j = 0; j < 16; ++j) {
        float o = bo[j];
        #pragma unroll
        for (int n = 0; n < 64; ++n) o += g_act4[b * 64 + n] * wo[j * 64 + n];
        res += o * wf[j];
    }
    out[b] = res;
}

extern "C" void kernel_launch(void* const* d_in, const int* in_sizes, int n_in,
                              void* d_out, int out_size) {
    const float* in  = (const float*)d_in[0];
    const float* cw  = (const float*)d_in[4];
    const float* cb  = (const float*)d_in[5];
    const float* w1  = (const float*)d_in[6];
    const float* b1  = (const float*)d_in[7];
    const float* w2  = (const float*)d_in[8];
    const float* b2  = (const float*)d_in[9];
    const float* w3  = (const float*)d_in[10];
    const float* b3  = (const float*)d_in[11];
    const float* w4  = (const float*)d_in[12];
    const float* b4  = (const float*)d_in[13];
    const float* wo  = (const float*)d_in[14];
    const float* bo  = (const float*)d_in[15];
    const float* wf  = (const float*)d_in[16];
    const float* bf  = (const float*)d_in[17];
    float* out = (float*)d_out;

    float *act0;
    uint4 *xpk0, *xpk1, *xpk2;
    cudaGetSymbolAddress((void**)&act0, g_act0);
    cudaGetSymbolAddress((void**)&xpk0, g_xpk0);
    cudaGetSymbolAddress((void**)&xpk1, g_xpk1);
    cudaGetSymbolAddress((void**)&xpk2, g_xpk2);

    conv_kernel<<<128, 128>>>(in, cw, cb);
    pack_kernel<<<672, 256>>>(act0, 21504, xpk0);

    // dense1: 16384x21504 -> 128 tiles x split 2, 168 slabs
    gemm_mma<<<dim3(128, 2), 256>>>(w1, xpk0, 16384, 21504, 168);
    reduce_pack<<<512, 256>>>(b1, 16384, 2, xpk1);

    // dense2: 4096x16384 -> 32 tiles x split 8, 32 slabs
    gemm_mma<<<dim3(32, 8), 256>>>(w2, xpk1, 4096, 16384, 32);
    reduce_pack<<<128, 256>>>(b2, 4096, 8, xpk2);

    // dense3: 4096x4096 -> 32 tiles x split 8, 8 slabs (fp32 out for dense4)
    gemm_mma<<<dim3(32, 8), 256>>>(w3, xpk2, 4096, 4096, 8);
    reduce_kernel<<<512, 256>>>(b3, 4096, 8);

    dense4_kernel<<<64, 128>>>(w4, b4);
    final_kernel<<<1, 32>>>(wo, bo, wf, bf, out);
}

// round 13
// speedup vs baseline: 1.0498x; 1.0498x over previous
#include <cuda_runtime.h>
#include <cstdint>

// ---------------- device scratch ----------------
__device__ __align__(16) float g_act0[32 * 21504];
__device__ __align__(16) float g_act3[32 * 4096];
__device__ __align__(16) float g_act4[32 * 64];
__device__ __align__(16) float g_part[2097152];        // 4*32*16384 == 16*32*4096
__device__ __align__(16) uint4 g_xpk0[172032];         // 21504/16 * 128
__device__ __align__(16) uint4 g_xpk1[131072];         // 16384/16 * 128
__device__ __align__(16) uint4 g_xpk2[32768];          // 4096/16 * 128

// ---------------- PTX helpers ----------------
__device__ __forceinline__ void mma16816(float* d, unsigned a0, unsigned a1, unsigned a2, unsigned a3,
                                         unsigned b0, unsigned b1) {
    asm volatile("mma.sync.aligned.m16n8k16.row.col.f32.bf16.bf16.f32 "
                 "{%0,%1,%2,%3}, {%4,%5,%6,%7}, {%8,%9}, {%0,%1,%2,%3};"
                 : "+f"(d[0]), "+f"(d[1]), "+f"(d[2]), "+f"(d[3])
                 : "r"(a0), "r"(a1), "r"(a2), "r"(a3), "r"(b0), "r"(b1));
}
// float4 -> {hi01, hi23, lo01, lo23} packed bf16x2
__device__ __forceinline__ void cvt_hilo(float4 v, unsigned &h01, unsigned &h23,
                                         unsigned &l01, unsigned &l23) {
    asm("cvt.rn.bf16x2.f32 %0, %1, %2;" : "=r"(h01) : "f"(v.y), "f"(v.x));
    asm("cvt.rn.bf16x2.f32 %0, %1, %2;" : "=r"(h23) : "f"(v.w), "f"(v.z));
    float r0 = v.x - __uint_as_float(h01 << 16);
    float r1 = v.y - __uint_as_float(h01 & 0xffff0000u);
    float r2 = v.z - __uint_as_float(h23 << 16);
    float r3 = v.w - __uint_as_float(h23 & 0xffff0000u);
    asm("cvt.rn.bf16x2.f32 %0, %1, %2;" : "=r"(l01) : "f"(r1), "f"(r0));
    asm("cvt.rn.bf16x2.f32 %0, %1, %2;" : "=r"(l23) : "f"(r3), "f"(r2));
}

// ---------------- conv + permuted scatter ----------------
__global__ void conv_kernel(const float* __restrict__ in,
                            const float* __restrict__ cw,
                            const float* __restrict__ cb) {
    int b = blockIdx.x >> 2, f = blockIdx.x & 3, tid = threadIdx.x;
    __shared__ float xin[343], wsh[128], bsh[16];
    for (int i = tid; i < 343; i += 128) xin[i] = in[(b * 343 + i) * 5 + f];
    if (tid < 128) wsh[tid] = cw[tid];
    if (tid < 16)  bsh[tid] = cb[tid];
    __syncthreads();
    int h = b >> 4, base = (b & 15) * 1344 + f * 336;
    for (int l = tid; l < 336; l += 128) {
        #pragma unroll
        for (int c = 0; c < 16; ++c) {
            float s = bsh[c];
            #pragma unroll
            for (int k = 0; k < 8; ++k) s += xin[l + k] * wsh[c * 8 + k];
            g_act0[(2 * c + h) * 21504 + base + l] = fmaxf(s, 0.f);
        }
    }
}

// ---------------- pack fp32 X[32][K] -> fragment-ordered bf16 hi/lo uint4 ----------------
__global__ void pack_kernel(const float* __restrict__ src, int K, uint4* __restrict__ dst) {
    int i = blockIdx.x * 256 + threadIdx.x;
    if (i >= (K >> 4) * 128) return;
    int kb = i >> 7, ng = (i >> 5) & 3, lane = i & 31;
    int b = ng * 8 + (lane >> 2), c = kb * 16 + (lane & 3) * 4;
    float4 v = *(const float4*)(src + (long)b * K + c);
    uint4 o;
    cvt_hilo(v, o.x, o.y, o.z, o.w);
    dst[i] = o;
}

// ---------------- split-K reduce + bias + relu -> packed X ----------------
__global__ void reduce_pack(const float* __restrict__ bias, int N, int ks, uint4* __restrict__ dst) {
    int i = blockIdx.x * 256 + threadIdx.x;
    if (i >= (N >> 4) * 128) return;
    int kb = i >> 7, ng = (i >> 5) & 3, lane = i & 31;
    int b = ng * 8 + (lane >> 2), c = kb * 16 + (lane & 3) * 4;
    float4 s = *(const float4*)(bias + c);
    for (int si = 0; si < ks; ++si) {
        float4 p = *(const float4*)(g_part + ((long)(si * 32 + b)) * N + c);
        s.x += p.x; s.y += p.y; s.z += p.z; s.w += p.w;
    }
    s.x = fmaxf(s.x, 0.f); s.y = fmaxf(s.y, 0.f);
    s.z = fmaxf(s.z, 0.f); s.w = fmaxf(s.w, 0.f);
    uint4 o;
    cvt_hilo(s, o.x, o.y, o.z, o.w);
    dst[i] = o;
}

// ---------------- split-K reduce + bias + relu -> fp32 (dense4 input) ----------------
__global__ void reduce_kernel(const float* __restrict__ bias, int N, int ks) {
    int idx = blockIdx.x * 256 + threadIdx.x;
    if (idx >= 32 * N) return;
    float s = bias[idx % N];
    for (int si = 0; si < ks; ++si) s += g_part[(long)si * 32 * N + idx];
    g_act3[idx] = fmaxf(s, 0.f);
}

// ---------------- bf16x3 mma.sync GEMM: M=256 x N=32 tile, warp = 32 rows x all N ----------------
// D[n,b] = sum_k W[n,k]*X[b,k]; slab k=64, split-K raw partials.
__global__ __launch_bounds__(256, 2)
void gemm_mma(const float* __restrict__ W, const uint4* __restrict__ xpk,
              int N, int K, int nslabs) {
    int tid = threadIdx.x, wid = tid >> 5, lane = tid & 31;
    int tile = blockIdx.x, ky = blockIdx.y;
    int r = lane >> 2, t = lane & 3;
    long k0 = (long)ky * nslabs * 64;

    const float* wp = W + (long)(tile * 256 + wid * 32 + r) * K + k0 + t * 4;
    long K8 = 8L * K, K16 = 16L * K;
    const uint4* xbase = xpk + (long)(ky * nslabs * 4) * 128 + lane;

    float acc[2][4][4];   // [m-frag][n-group][4]
    #pragma unroll
    for (int mi = 0; mi < 2; ++mi)
        #pragma unroll
        for (int j = 0; j < 4; ++j)
            #pragma unroll
            for (int q = 0; q < 4; ++q) acc[mi][j][q] = 0.f;

    for (int s = 0; s < nslabs; ++s) {
        long sk = (long)s * 64;
        #pragma unroll
        for (int ks = 0; ks < 4; ++ks) {
            long ko = sk + ks * 16;
            unsigned ah[2][4], al[2][4];
            #pragma unroll
            for (int mi = 0; mi < 2; ++mi) {
                float4 w0 = __ldg((const float4*)(wp + mi * K16 + ko));
                float4 w1 = __ldg((const float4*)(wp + mi * K16 + K8 + ko));
                cvt_hilo(w0, ah[mi][0], ah[mi][2], al[mi][0], al[mi][2]);  // row r
                cvt_hilo(w1, ah[mi][1], ah[mi][3], al[mi][1], al[mi][3]);  // row r+8
            }
            const uint4* xq = xbase + (long)(s * 4 + ks) * 128;
            #pragma unroll
            for (int j = 0; j < 4; ++j) {
                uint4 u = __ldg(xq + j * 32);    // {bh0, bh1, bl0, bl1}
                #pragma unroll
                for (int mi = 0; mi < 2; ++mi) {
                    mma16816(acc[mi][j], ah[mi][0], ah[mi][1], ah[mi][2], ah[mi][3], u.x, u.y);
                    mma16816(acc[mi][j], ah[mi][0], ah[mi][1], ah[mi][2], ah[mi][3], u.z, u.w);
                    mma16816(acc[mi][j], al[mi][0], al[mi][1], al[mi][2], al[mi][3], u.x, u.y);
                }
            }
        }
    }

    // epilogue: raw split-K partials (fragment mapping validated R10/R11)
    #pragma unroll
    for (int mi = 0; mi < 2; ++mi) {
        int n0 = tile * 256 + wid * 32 + mi * 16 + r;
        #pragma unroll
        for (int nf = 0; nf < 4; ++nf) {
            int b0 = nf * 8 + 2 * t;
            g_part[(long)(ky * 32 + b0)     * N + n0]     = acc[mi][nf][0];
            g_part[(long)(ky * 32 + b0 + 1) * N + n0]     = acc[mi][nf][1];
            g_part[(long)(ky * 32 + b0)     * N + n0 + 8] = acc[mi][nf][2];
            g_part[(long)(ky * 32 + b0 + 1) * N + n0 + 8] = acc[mi][nf][3];
        }
    }
}

// ---------------- dense4 (4096 -> 64) ----------------
__global__ void dense4_kernel(const float* __restrict__ w4, const float* __restrict__ b4) {
    int n = blockIdx.x, tid = threadIdx.x;
    float acc[32];
    #pragma unroll
    for (int b = 0; b < 32; ++b) acc[b] = 0.f;
    const float* wr = w4 + n * 4096;
    for (int k = tid; k < 4096; k += 128) {
        float w = wr[k];
        #pragma unroll
        for (int b = 0; b < 32; ++b) acc[b] += g_act3[b * 4096 + k] * w;
    }
    __shared__ float red[4][32];
    int lane = tid & 31, wrp = tid >> 5;
    #pragma unroll
    for (int b = 0; b < 32; ++b) {
        float v = acc[b];
        v += __shfl_down_sync(0xffffffffu, v, 16);
        v += __shfl_down_sync(0xffffffffu, v, 8);
        v += __shfl_down_sync(0xffffffffu, v, 4);
        v += __shfl_down_sync(0xffffffffu, v, 2);
        v += __shfl_down_sync(0xffffffffu, v, 1);
        if (lane == 0) red[wrp][b] = v;
    }
    __syncthreads();
    if (tid < 32) {
        float s = red[0][tid] + red[1][tid] + red[2][tid] + red[3][tid] + b4[n];
        g_act4[tid * 64 + n] = fmaxf(s, 0.f);
    }
}

// ---------------- fused output (64 -> 16 -> 1) ----------------
__global__ void final_kernel(const float* __restrict__ wo, const float* __restrict__ bo,
                             const float* __restrict__ wf, const float* __restrict__ bf,
                             float* __restrict__ out) {
    int b = threadIdx.x;
    float res = bf[0];
    for (int j = 0; j < 16; ++j) {
        float o = bo[j];
        #pragma unroll
        for (int n = 0; n < 64; ++n) o += g_act4[b * 64 + n] * wo[j * 64 + n];
        res += o * wf[j];
    }
    out[b] = res;
}

extern "C" void kernel_launch(void* const* d_in, const int* in_sizes, int n_in,
                              void* d_out, int out_size) {
    const float* in  = (const float*)d_in[0];
    const float* cw  = (const float*)d_in[4];
    const float* cb  = (const float*)d_in[5];
    const float* w1  = (const float*)d_in[6];
    const float* b1  = (const float*)d_in[7];
    const float* w2  = (const float*)d_in[8];
    const float* b2  = (const float*)d_in[9];
    const float* w3  = (const float*)d_in[10];
    const float* b3  = (const float*)d_in[11];
    const float* w4  = (const float*)d_in[12];
    const float* b4  = (const float*)d_in[13];
    const float* wo  = (const float*)d_in[14];
    const float* bo  = (const float*)d_in[15];
    const float* wf  = (const float*)d_in[16];
    const float* bf  = (const float*)d_in[17];
    float* out = (float*)d_out;

    float *act0;
    uint4 *xpk0, *xpk1, *xpk2;
    cudaGetSymbolAddress((void**)&act0, g_act0);
    cudaGetSymbolAddress((void**)&xpk0, g_xpk0);
    cudaGetSymbolAddress((void**)&xpk1, g_xpk1);
    cudaGetSymbolAddress((void**)&xpk2, g_xpk2);

    conv_kernel<<<128, 128>>>(in, cw, cb);
    pack_kernel<<<672, 256>>>(act0, 21504, xpk0);

    // dense1: 16384x21504 -> 64 tiles (M=256) x split 4 = 256 CTAs, 84 slabs
    gemm_mma<<<dim3(64, 4), 256>>>(w1, xpk0, 16384, 21504, 84);
    reduce_pack<<<512, 256>>>(b1, 16384, 4, xpk1);

    // dense2: 4096x16384 -> 16 tiles x split 16 = 256 CTAs, 16 slabs
    gemm_mma<<<dim3(16, 16), 256>>>(w2, xpk1, 4096, 16384, 16);
    reduce_pack<<<128, 256>>>(b2, 4096, 16, xpk2);

    // dense3: 4096x4096 -> 16 tiles x split 16 = 256 CTAs, 4 slabs (fp32 out for dense4)
    gemm_mma<<<dim3(16, 16), 256>>>(w3, xpk2, 4096, 4096, 4);
    reduce_kernel<<<512, 256>>>(b3, 4096, 16);

    dense4_kernel<<<64, 128>>>(w4, b4);
    final_kernel<<<1, 32>>>(wo, bo, wf, bf, out);
}